// round 5
// baseline (speedup 1.0000x reference)
#include <cuda_runtime.h>
#include <math.h>
#include <stdint.h>

// ===========================================================================
// Attention_49185965473896 — mma.sync tf32 (sm_100), round 5
//   B=4, T=2048, C=1024 fp32.
// Changes vs round 4:
//   - RoPE fused into Q/K projection epilogue (register-resident pairs)
//   - V projection writes V^T directly (smem-staged transposed epilogue)
//   - STAGES 5->4, __launch_bounds__(256,2) for 2 CTAs/SM
// ===========================================================================

#define TT 2048
#define CC 1024
#define NB 4
#define MTOT (NB * TT)

#define BM 128
#define BN 128
#define BK 16
#define PITCH 20                       // floats per smem row (16 data + 4 pad)
#define STAGES 4
#define STAGE_FLOATS ((BM + BN) * PITCH)           // 5120
#define SMEM_BYTES   (STAGES * STAGE_FLOATS * 4)   // 81920
#define TPITCH 133                     // transpose-stage pitch (conflict-free)

// Scratch (static device arrays; allocation is forbidden)
__device__ float g_Q [(size_t)NB * TT * CC];
__device__ float g_K [(size_t)NB * TT * CC];
__device__ float g_Vt[(size_t)CC * NB * TT];   // [C][B*T]
__device__ float g_O [(size_t)NB * TT * CC];
__device__ float g_S [(size_t)NB * TT * TT];
__device__ float g_Wt[(size_t)4 * CC * CC];

// ---------------------------------------------------------------------------
__device__ __forceinline__ uint32_t smem_u32(const void* p) {
    uint32_t a;
    asm("{ .reg .u64 t; cvta.to.shared.u64 t, %1; cvt.u32.u64 %0, t; }"
        : "=r"(a) : "l"(p));
    return a;
}
__device__ __forceinline__ void cp_async16(uint32_t s, const void* g) {
    asm volatile("cp.async.cg.shared.global [%0], [%1], 16;\n" :: "r"(s), "l"(g));
}
__device__ __forceinline__ uint32_t f2tf(float x) {
    uint32_t r;
    asm("cvt.rna.tf32.f32 %0, %1;" : "=r"(r) : "f"(x));
    return r;
}
__device__ __forceinline__ void mma8(float& c0, float& c1, float& c2, float& c3,
                                     uint32_t a0, uint32_t a1, uint32_t a2, uint32_t a3,
                                     uint32_t b0, uint32_t b1) {
    asm volatile(
        "mma.sync.aligned.m16n8k8.row.col.f32.tf32.tf32.f32 "
        "{%0,%1,%2,%3}, {%4,%5,%6,%7}, {%8,%9}, {%0,%1,%2,%3};"
        : "+f"(c0), "+f"(c1), "+f"(c2), "+f"(c3)
        : "r"(a0), "r"(a1), "r"(a2), "r"(a3), "r"(b0), "r"(b1));
}

// ---------------------------------------------------------------------------
// MODE: 0 = PROJ (+bias)
//       1 = PROJ -> V^T (+bias, transposed smem-staged epilogue)
//       2 = SCORES (scale; tiles with n0>m0 skipped)
//       3 = PV (K truncated at m0+BM)
//       4 = PROJ + RoPE (+bias, in-register rotation)
// ---------------------------------------------------------------------------
template<int MODE>
__global__ __launch_bounds__(256, 2) void mma_kernel(
    const float* __restrict__ A, const float* __restrict__ Bm,
    const float* __restrict__ bias, float* __restrict__ Out,
    int pitchA, int pitchB)
{
    const int m0 = blockIdx.y * BM;
    const int n0 = blockIdx.x * BN;
    const int z  = blockIdx.z;

    if (MODE == 2 && n0 > m0) return;   // strictly-upper tile: nothing to do

    extern __shared__ float smem[];
    const int tid = threadIdx.x;
    const int wid = tid >> 5;
    const int lane = tid & 31;
    const int g = lane >> 2;            // group id 0..7
    const int tg = lane & 3;            // thread-in-group 0..3
    const int wm = wid & 3;             // warp row (4 x 32 rows)
    const int wn = wid >> 2;            // warp col (2 x 64 cols)

    // geometry
    const float* Abase;
    const float* Bbase;
    float* OutB;
    int Klen, outPitch;
    if (MODE == 0 || MODE == 1 || MODE == 4) {
        Abase = A + (size_t)m0 * pitchA;
        Bbase = Bm + (size_t)n0 * pitchB;
        OutB = Out; Klen = CC; outPitch = CC;
    } else if (MODE == 2) {
        Abase = A + ((size_t)z * TT + m0) * pitchA;
        Bbase = Bm + ((size_t)z * TT + n0) * pitchB;
        OutB = Out + (size_t)z * TT * TT; Klen = CC; outPitch = TT;
    } else {
        Abase = A + ((size_t)z * TT + m0) * pitchA;
        Bbase = Bm + (size_t)n0 * pitchB + (size_t)z * TT;  // Vt: [C][B*T]
        OutB = Out + (size_t)z * TT * CC; Klen = m0 + BM; outPitch = CC;
    }
    const int KT = Klen / BK;

    float acc[2][8][4];
    #pragma unroll
    for (int mt = 0; mt < 2; mt++)
        #pragma unroll
        for (int nt = 0; nt < 8; nt++)
            #pragma unroll
            for (int c = 0; c < 4; c++) acc[mt][nt][c] = 0.0f;

    // per-thread load geometry: 2 x 16B for A, 2 x 16B for B
    const int r0c = tid >> 2;
    const int o0c = (tid & 3) * 4;
    const int r1c = (tid + 256) >> 2;
    const int o1c = o0c;

    auto load_stage = [&](int kt, int slot) {
        float* dA = smem + slot * STAGE_FLOATS;
        float* dB = dA + BM * PITCH;
        const int k0 = kt * BK;
        cp_async16(smem_u32(dA + r0c * PITCH + o0c), Abase + (size_t)r0c * pitchA + k0 + o0c);
        cp_async16(smem_u32(dA + r1c * PITCH + o1c), Abase + (size_t)r1c * pitchA + k0 + o1c);
        cp_async16(smem_u32(dB + r0c * PITCH + o0c), Bbase + (size_t)r0c * pitchB + k0 + o0c);
        cp_async16(smem_u32(dB + r1c * PITCH + o1c), Bbase + (size_t)r1c * pitchB + k0 + o1c);
    };

    // prologue: prefetch STAGES-1 stages (KT >= 8 always)
    #pragma unroll
    for (int s = 0; s < STAGES - 1; s++) {
        load_stage(s, s);
        asm volatile("cp.async.commit_group;\n" ::);
    }

    for (int kt = 0; kt < KT; kt++) {
        asm volatile("cp.async.wait_group %0;\n" :: "n"(STAGES - 2));
        __syncthreads();

        const int nf = kt + STAGES - 1;
        if (nf < KT) load_stage(nf, nf % STAGES);
        asm volatile("cp.async.commit_group;\n" ::);

        const float* sA = smem + (kt % STAGES) * STAGE_FLOATS;
        const float* sB = sA + BM * PITCH;

        #pragma unroll
        for (int ks = 0; ks < 2; ks++) {
            uint32_t af[2][4], bf[8][2];
            #pragma unroll
            for (int mt = 0; mt < 2; mt++) {
                const float* p = sA + (wm * 32 + mt * 16 + g) * PITCH + ks * 8 + tg;
                af[mt][0] = f2tf(p[0]);
                af[mt][1] = f2tf(p[8 * PITCH]);
                af[mt][2] = f2tf(p[4]);
                af[mt][3] = f2tf(p[8 * PITCH + 4]);
            }
            #pragma unroll
            for (int nt = 0; nt < 8; nt++) {
                const float* p = sB + (wn * 64 + nt * 8 + g) * PITCH + ks * 8 + tg;
                bf[nt][0] = f2tf(p[0]);
                bf[nt][1] = f2tf(p[4]);
            }
            #pragma unroll
            for (int mt = 0; mt < 2; mt++)
                #pragma unroll
                for (int nt = 0; nt < 8; nt++)
                    mma8(acc[mt][nt][0], acc[mt][nt][1], acc[mt][nt][2], acc[mt][nt][3],
                         af[mt][0], af[mt][1], af[mt][2], af[mt][3],
                         bf[nt][0], bf[nt][1]);
        }
    }

    // ------------------------- epilogues -------------------------
    const float scale = rsqrtf((float)CC);

    if (MODE == 1) {
        // V^T path: stage tile in smem, write transposed coalesced.
        __syncthreads();   // mainloop smem fully consumed
        float* stage = smem;   // 128 x TPITCH floats = 68096 B < SMEM_BYTES
        #pragma unroll
        for (int mt = 0; mt < 2; mt++) {
            const int r = wm * 32 + mt * 16 + g;
            #pragma unroll
            for (int nt = 0; nt < 8; nt++) {
                const int cl = wn * 64 + nt * 8 + 2 * tg;
                const float b0 = __ldg(&bias[n0 + cl]);
                const float b1 = __ldg(&bias[n0 + cl + 1]);
                stage[r * TPITCH + cl]           = acc[mt][nt][0] + b0;
                stage[r * TPITCH + cl + 1]       = acc[mt][nt][1] + b1;
                stage[(r + 8) * TPITCH + cl]     = acc[mt][nt][2] + b0;
                stage[(r + 8) * TPITCH + cl + 1] = acc[mt][nt][3] + b1;
            }
        }
        __syncthreads();
        const int tl = tid & 127;
        const int nh = tid >> 7;
        #pragma unroll 4
        for (int it = 0; it < 64; it++) {
            const int nl = it * 2 + nh;
            Out[(size_t)(n0 + nl) * MTOT + m0 + tl] = stage[tl * TPITCH + nl];
        }
        return;
    }

    #pragma unroll
    for (int mt = 0; mt < 2; mt++) {
        const int row = m0 + wm * 32 + mt * 16 + g;
        #pragma unroll
        for (int nt = 0; nt < 8; nt++) {
            const int col = n0 + wn * 64 + nt * 8 + 2 * tg;
            float c0 = acc[mt][nt][0], c1 = acc[mt][nt][1];
            float c2 = acc[mt][nt][2], c3 = acc[mt][nt][3];
            if (MODE == 0 || MODE == 4) {
                const float b0 = __ldg(&bias[col]);
                const float b1 = __ldg(&bias[col + 1]);
                c0 += b0; c1 += b1; c2 += b0; c3 += b1;
            }
            if (MODE == 4) {
                // interleaved RoPE: (c0,c1) pair at t=row, (c2,c3) at t=row+8
                const float invf = powf(10000.0f, -(float)col / (float)CC);
                const int t = row & (TT - 1);
                float s0, co0, s8, co8;
                sincosf((float)t * invf, &s0, &co0);
                sincosf((float)(t + 8) * invf, &s8, &co8);
                const float e0 = c0, o0 = c1, e8 = c2, o8 = c3;
                c0 = e0 * co0 - o0 * s0;
                c1 = o0 * co0 + e0 * s0;
                c2 = e8 * co8 - o8 * s8;
                c3 = o8 * co8 + e8 * s8;
            }
            if (MODE == 2) {
                c0 *= scale; c1 *= scale; c2 *= scale; c3 *= scale;
            }
            *reinterpret_cast<float2*>(&OutB[(size_t)row * outPitch + col]) =
                make_float2(c0, c1);
            *reinterpret_cast<float2*>(&OutB[(size_t)(row + 8) * outPitch + col]) =
                make_float2(c2, c3);
        }
    }
}

// ---------------------------------------------------------------------------
// Transpose: dst[c][r] = src[r][c], R x Ccols -> Ccols x R (both mult of 32)
// ---------------------------------------------------------------------------
__global__ void transpose_kernel(const float* __restrict__ src, float* __restrict__ dst,
                                 int R, int Ccols)
{
    __shared__ float tile[32][33];
    const int tx = threadIdx.x, ty = threadIdx.y;
    const int x = blockIdx.x * 32 + tx;
    const int y = blockIdx.y * 32 + ty;
    #pragma unroll
    for (int i = 0; i < 32; i += 8)
        tile[ty + i][tx] = src[(size_t)(y + i) * Ccols + x];
    __syncthreads();
    const int x2 = blockIdx.y * 32 + tx;
    const int y2 = blockIdx.x * 32 + ty;
    #pragma unroll
    for (int i = 0; i < 32; i += 8)
        dst[(size_t)(y2 + i) * R + x2] = tile[tx][ty + i];
}

// ---------------------------------------------------------------------------
// Causal softmax over valid prefix [0, i]; zero-fills (i, tile_end).
// ---------------------------------------------------------------------------
__global__ __launch_bounds__(256) void softmax_kernel(float* __restrict__ S)
{
    float* p = S + (size_t)blockIdx.x * TT;
    const int i = blockIdx.x & (TT - 1);
    const int len = i + 1;
    const int tend = ((i >> 7) + 1) << 7;   // round up to 128 (= BN)
    __shared__ float red[256];
    const int tid = threadIdx.x;

    float m = -3.4e38f;
    for (int j = tid; j < len; j += 256) m = fmaxf(m, p[j]);
    red[tid] = m;
    __syncthreads();
    for (int s = 128; s > 0; s >>= 1) {
        if (tid < s) red[tid] = fmaxf(red[tid], red[tid + s]);
        __syncthreads();
    }
    m = red[0];
    __syncthreads();

    float sum = 0.0f;
    for (int j = tid; j < tend; j += 256) {
        if (j < len) {
            float e = expf(p[j] - m);
            p[j] = e;
            sum += e;
        } else {
            p[j] = 0.0f;
        }
    }
    red[tid] = sum;
    __syncthreads();
    for (int s = 128; s > 0; s >>= 1) {
        if (tid < s) red[tid] += red[tid + s];
        __syncthreads();
    }
    const float inv = 1.0f / red[0];
    for (int j = tid; j < len; j += 256) p[j] *= inv;
}

// ---------------------------------------------------------------------------
extern "C" void kernel_launch(void* const* d_in, const int* in_sizes, int n_in,
                              void* d_out, int out_size)
{
    const float* x  = (const float*)d_in[0];
    const float* Wq = (const float*)d_in[1];
    const float* bq = (const float*)d_in[2];
    const float* Wk = (const float*)d_in[3];
    const float* bk = (const float*)d_in[4];
    const float* Wv = (const float*)d_in[5];
    const float* bv = (const float*)d_in[6];
    const float* Wo = (const float*)d_in[7];
    const float* bo = (const float*)d_in[8];

    float *Q, *K, *Vt, *O, *S, *Wt;
    cudaGetSymbolAddress((void**)&Q,  g_Q);
    cudaGetSymbolAddress((void**)&K,  g_K);
    cudaGetSymbolAddress((void**)&Vt, g_Vt);
    cudaGetSymbolAddress((void**)&O,  g_O);
    cudaGetSymbolAddress((void**)&S,  g_S);
    cudaGetSymbolAddress((void**)&Wt, g_Wt);

    cudaFuncSetAttribute(mma_kernel<0>, cudaFuncAttributeMaxDynamicSharedMemorySize, SMEM_BYTES);
    cudaFuncSetAttribute(mma_kernel<1>, cudaFuncAttributeMaxDynamicSharedMemorySize, SMEM_BYTES);
    cudaFuncSetAttribute(mma_kernel<2>, cudaFuncAttributeMaxDynamicSharedMemorySize, SMEM_BYTES);
    cudaFuncSetAttribute(mma_kernel<3>, cudaFuncAttributeMaxDynamicSharedMemorySize, SMEM_BYTES);
    cudaFuncSetAttribute(mma_kernel<4>, cudaFuncAttributeMaxDynamicSharedMemorySize, SMEM_BYTES);

    // weight transposes (Wt[n][k] = W[k][n])
    dim3 tb(32, 8);
    dim3 tgw(CC / 32, CC / 32);
    transpose_kernel<<<tgw, tb>>>(Wq, Wt + 0 * (size_t)CC * CC, CC, CC);
    transpose_kernel<<<tgw, tb>>>(Wk, Wt + 1 * (size_t)CC * CC, CC, CC);
    transpose_kernel<<<tgw, tb>>>(Wv, Wt + 2 * (size_t)CC * CC, CC, CC);
    transpose_kernel<<<tgw, tb>>>(Wo, Wt + 3 * (size_t)CC * CC, CC, CC);

    // projections (RoPE fused for Q/K; V writes V^T directly)
    dim3 gproj(CC / BN, MTOT / BM, 1);
    mma_kernel<4><<<gproj, 256, SMEM_BYTES>>>(x, Wt + 0 * (size_t)CC * CC, bq, Q, CC, CC);
    mma_kernel<4><<<gproj, 256, SMEM_BYTES>>>(x, Wt + 1 * (size_t)CC * CC, bk, K, CC, CC);
    mma_kernel<1><<<gproj, 256, SMEM_BYTES>>>(x, Wt + 2 * (size_t)CC * CC, bv, Vt, CC, CC);

    // scores: S = QK^T * rsqrt(C), lower/diag tiles only
    dim3 gsc(TT / BN, TT / BM, NB);
    mma_kernel<2><<<gsc, 256, SMEM_BYTES>>>(Q, K, nullptr, S, CC, CC);

    softmax_kernel<<<MTOT, 256>>>(S);

    // O = P @ V
    dim3 gpv(CC / BN, TT / BM, NB);
    mma_kernel<3><<<gpv, 256, SMEM_BYTES>>>(S, Vt, nullptr, O, TT, MTOT);

    // out = O @ Wo + bo
    mma_kernel<0><<<gproj, 256, SMEM_BYTES>>>(O, Wt + 3 * (size_t)CC * CC, bo, (float*)d_out, CC, CC);

    (void)n_in; (void)out_size; (void)in_sizes;
}

// round 6
// speedup vs baseline: 1.0001x; 1.0001x over previous
#include <cuda_runtime.h>
#include <math.h>
#include <stdint.h>

// ===========================================================================
// Attention_49185965473896 — mma.sync tf32 (sm_100), round 5
//   B=4, T=2048, C=1024 fp32.
// Changes vs round 4:
//   - RoPE fused into Q/K projection epilogue (register-resident pairs)
//   - V projection writes V^T directly (smem-staged transposed epilogue)
//   - STAGES 5->4, __launch_bounds__(256,2) for 2 CTAs/SM
// ===========================================================================

#define TT 2048
#define CC 1024
#define NB 4
#define MTOT (NB * TT)

#define BM 128
#define BN 128
#define BK 16
#define PITCH 20                       // floats per smem row (16 data + 4 pad)
#define STAGES 4
#define STAGE_FLOATS ((BM + BN) * PITCH)           // 5120
#define SMEM_BYTES   (STAGES * STAGE_FLOATS * 4)   // 81920
#define TPITCH 133                     // transpose-stage pitch (conflict-free)

// Scratch (static device arrays; allocation is forbidden)
__device__ float g_Q [(size_t)NB * TT * CC];
__device__ float g_K [(size_t)NB * TT * CC];
__device__ float g_Vt[(size_t)CC * NB * TT];   // [C][B*T]
__device__ float g_O [(size_t)NB * TT * CC];
__device__ float g_S [(size_t)NB * TT * TT];
__device__ float g_Wt[(size_t)4 * CC * CC];

// ---------------------------------------------------------------------------
__device__ __forceinline__ uint32_t smem_u32(const void* p) {
    uint32_t a;
    asm("{ .reg .u64 t; cvta.to.shared.u64 t, %1; cvt.u32.u64 %0, t; }"
        : "=r"(a) : "l"(p));
    return a;
}
__device__ __forceinline__ void cp_async16(uint32_t s, const void* g) {
    asm volatile("cp.async.cg.shared.global [%0], [%1], 16;\n" :: "r"(s), "l"(g));
}
__device__ __forceinline__ uint32_t f2tf(float x) {
    uint32_t r;
    asm("cvt.rna.tf32.f32 %0, %1;" : "=r"(r) : "f"(x));
    return r;
}
__device__ __forceinline__ void mma8(float& c0, float& c1, float& c2, float& c3,
                                     uint32_t a0, uint32_t a1, uint32_t a2, uint32_t a3,
                                     uint32_t b0, uint32_t b1) {
    asm volatile(
        "mma.sync.aligned.m16n8k8.row.col.f32.tf32.tf32.f32 "
        "{%0,%1,%2,%3}, {%4,%5,%6,%7}, {%8,%9}, {%0,%1,%2,%3};"
        : "+f"(c0), "+f"(c1), "+f"(c2), "+f"(c3)
        : "r"(a0), "r"(a1), "r"(a2), "r"(a3), "r"(b0), "r"(b1));
}

// ---------------------------------------------------------------------------
// MODE: 0 = PROJ (+bias)
//       1 = PROJ -> V^T (+bias, transposed smem-staged epilogue)
//       2 = SCORES (scale; tiles with n0>m0 skipped)
//       3 = PV (K truncated at m0+BM)
//       4 = PROJ + RoPE (+bias, in-register rotation)
// ---------------------------------------------------------------------------
template<int MODE>
__global__ __launch_bounds__(256, 2) void mma_kernel(
    const float* __restrict__ A, const float* __restrict__ Bm,
    const float* __restrict__ bias, float* __restrict__ Out,
    int pitchA, int pitchB)
{
    const int m0 = blockIdx.y * BM;
    const int n0 = blockIdx.x * BN;
    const int z  = blockIdx.z;

    if (MODE == 2 && n0 > m0) return;   // strictly-upper tile: nothing to do

    extern __shared__ float smem[];
    const int tid = threadIdx.x;
    const int wid = tid >> 5;
    const int lane = tid & 31;
    const int g = lane >> 2;            // group id 0..7
    const int tg = lane & 3;            // thread-in-group 0..3
    const int wm = wid & 3;             // warp row (4 x 32 rows)
    const int wn = wid >> 2;            // warp col (2 x 64 cols)

    // geometry
    const float* Abase;
    const float* Bbase;
    float* OutB;
    int Klen, outPitch;
    if (MODE == 0 || MODE == 1 || MODE == 4) {
        Abase = A + (size_t)m0 * pitchA;
        Bbase = Bm + (size_t)n0 * pitchB;
        OutB = Out; Klen = CC; outPitch = CC;
    } else if (MODE == 2) {
        Abase = A + ((size_t)z * TT + m0) * pitchA;
        Bbase = Bm + ((size_t)z * TT + n0) * pitchB;
        OutB = Out + (size_t)z * TT * TT; Klen = CC; outPitch = TT;
    } else {
        Abase = A + ((size_t)z * TT + m0) * pitchA;
        Bbase = Bm + (size_t)n0 * pitchB + (size_t)z * TT;  // Vt: [C][B*T]
        OutB = Out + (size_t)z * TT * CC; Klen = m0 + BM; outPitch = CC;
    }
    const int KT = Klen / BK;

    float acc[2][8][4];
    #pragma unroll
    for (int mt = 0; mt < 2; mt++)
        #pragma unroll
        for (int nt = 0; nt < 8; nt++)
            #pragma unroll
            for (int c = 0; c < 4; c++) acc[mt][nt][c] = 0.0f;

    // per-thread load geometry: 2 x 16B for A, 2 x 16B for B
    const int r0c = tid >> 2;
    const int o0c = (tid & 3) * 4;
    const int r1c = (tid + 256) >> 2;
    const int o1c = o0c;

    auto load_stage = [&](int kt, int slot) {
        float* dA = smem + slot * STAGE_FLOATS;
        float* dB = dA + BM * PITCH;
        const int k0 = kt * BK;
        cp_async16(smem_u32(dA + r0c * PITCH + o0c), Abase + (size_t)r0c * pitchA + k0 + o0c);
        cp_async16(smem_u32(dA + r1c * PITCH + o1c), Abase + (size_t)r1c * pitchA + k0 + o1c);
        cp_async16(smem_u32(dB + r0c * PITCH + o0c), Bbase + (size_t)r0c * pitchB + k0 + o0c);
        cp_async16(smem_u32(dB + r1c * PITCH + o1c), Bbase + (size_t)r1c * pitchB + k0 + o1c);
    };

    // prologue: prefetch STAGES-1 stages (KT >= 8 always)
    #pragma unroll
    for (int s = 0; s < STAGES - 1; s++) {
        load_stage(s, s);
        asm volatile("cp.async.commit_group;\n" ::);
    }

    for (int kt = 0; kt < KT; kt++) {
        asm volatile("cp.async.wait_group %0;\n" :: "n"(STAGES - 2));
        __syncthreads();

        const int nf = kt + STAGES - 1;
        if (nf < KT) load_stage(nf, nf % STAGES);
        asm volatile("cp.async.commit_group;\n" ::);

        const float* sA = smem + (kt % STAGES) * STAGE_FLOATS;
        const float* sB = sA + BM * PITCH;

        #pragma unroll
        for (int ks = 0; ks < 2; ks++) {
            uint32_t af[2][4], bf[8][2];
            #pragma unroll
            for (int mt = 0; mt < 2; mt++) {
                const float* p = sA + (wm * 32 + mt * 16 + g) * PITCH + ks * 8 + tg;
                af[mt][0] = f2tf(p[0]);
                af[mt][1] = f2tf(p[8 * PITCH]);
                af[mt][2] = f2tf(p[4]);
                af[mt][3] = f2tf(p[8 * PITCH + 4]);
            }
            #pragma unroll
            for (int nt = 0; nt < 8; nt++) {
                const float* p = sB + (wn * 64 + nt * 8 + g) * PITCH + ks * 8 + tg;
                bf[nt][0] = f2tf(p[0]);
                bf[nt][1] = f2tf(p[4]);
            }
            #pragma unroll
            for (int mt = 0; mt < 2; mt++)
                #pragma unroll
                for (int nt = 0; nt < 8; nt++)
                    mma8(acc[mt][nt][0], acc[mt][nt][1], acc[mt][nt][2], acc[mt][nt][3],
                         af[mt][0], af[mt][1], af[mt][2], af[mt][3],
                         bf[nt][0], bf[nt][1]);
        }
    }

    // ------------------------- epilogues -------------------------
    const float scale = rsqrtf((float)CC);

    if (MODE == 1) {
        // V^T path: stage tile in smem, write transposed coalesced.
        __syncthreads();   // mainloop smem fully consumed
        float* stage = smem;   // 128 x TPITCH floats = 68096 B < SMEM_BYTES
        #pragma unroll
        for (int mt = 0; mt < 2; mt++) {
            const int r = wm * 32 + mt * 16 + g;
            #pragma unroll
            for (int nt = 0; nt < 8; nt++) {
                const int cl = wn * 64 + nt * 8 + 2 * tg;
                const float b0 = __ldg(&bias[n0 + cl]);
                const float b1 = __ldg(&bias[n0 + cl + 1]);
                stage[r * TPITCH + cl]           = acc[mt][nt][0] + b0;
                stage[r * TPITCH + cl + 1]       = acc[mt][nt][1] + b1;
                stage[(r + 8) * TPITCH + cl]     = acc[mt][nt][2] + b0;
                stage[(r + 8) * TPITCH + cl + 1] = acc[mt][nt][3] + b1;
            }
        }
        __syncthreads();
        const int tl = tid & 127;
        const int nh = tid >> 7;
        #pragma unroll 4
        for (int it = 0; it < 64; it++) {
            const int nl = it * 2 + nh;
            Out[(size_t)(n0 + nl) * MTOT + m0 + tl] = stage[tl * TPITCH + nl];
        }
        return;
    }

    #pragma unroll
    for (int mt = 0; mt < 2; mt++) {
        const int row = m0 + wm * 32 + mt * 16 + g;
        #pragma unroll
        for (int nt = 0; nt < 8; nt++) {
            const int col = n0 + wn * 64 + nt * 8 + 2 * tg;
            float c0 = acc[mt][nt][0], c1 = acc[mt][nt][1];
            float c2 = acc[mt][nt][2], c3 = acc[mt][nt][3];
            if (MODE == 0 || MODE == 4) {
                const float b0 = __ldg(&bias[col]);
                const float b1 = __ldg(&bias[col + 1]);
                c0 += b0; c1 += b1; c2 += b0; c3 += b1;
            }
            if (MODE == 4) {
                // interleaved RoPE: (c0,c1) pair at t=row, (c2,c3) at t=row+8
                const float invf = powf(10000.0f, -(float)col / (float)CC);
                const int t = row & (TT - 1);
                float s0, co0, s8, co8;
                sincosf((float)t * invf, &s0, &co0);
                sincosf((float)(t + 8) * invf, &s8, &co8);
                const float e0 = c0, o0 = c1, e8 = c2, o8 = c3;
                c0 = e0 * co0 - o0 * s0;
                c1 = o0 * co0 + e0 * s0;
                c2 = e8 * co8 - o8 * s8;
                c3 = o8 * co8 + e8 * s8;
            }
            if (MODE == 2) {
                c0 *= scale; c1 *= scale; c2 *= scale; c3 *= scale;
            }
            *reinterpret_cast<float2*>(&OutB[(size_t)row * outPitch + col]) =
                make_float2(c0, c1);
            *reinterpret_cast<float2*>(&OutB[(size_t)(row + 8) * outPitch + col]) =
                make_float2(c2, c3);
        }
    }
}

// ---------------------------------------------------------------------------
// Transpose: dst[c][r] = src[r][c], R x Ccols -> Ccols x R (both mult of 32)
// ---------------------------------------------------------------------------
__global__ void transpose_kernel(const float* __restrict__ src, float* __restrict__ dst,
                                 int R, int Ccols)
{
    __shared__ float tile[32][33];
    const int tx = threadIdx.x, ty = threadIdx.y;
    const int x = blockIdx.x * 32 + tx;
    const int y = blockIdx.y * 32 + ty;
    #pragma unroll
    for (int i = 0; i < 32; i += 8)
        tile[ty + i][tx] = src[(size_t)(y + i) * Ccols + x];
    __syncthreads();
    const int x2 = blockIdx.y * 32 + tx;
    const int y2 = blockIdx.x * 32 + ty;
    #pragma unroll
    for (int i = 0; i < 32; i += 8)
        dst[(size_t)(y2 + i) * R + x2] = tile[tx][ty + i];
}

// ---------------------------------------------------------------------------
// Causal softmax over valid prefix [0, i]; zero-fills (i, tile_end).
// ---------------------------------------------------------------------------
__global__ __launch_bounds__(256) void softmax_kernel(float* __restrict__ S)
{
    float* p = S + (size_t)blockIdx.x * TT;
    const int i = blockIdx.x & (TT - 1);
    const int len = i + 1;
    const int tend = ((i >> 7) + 1) << 7;   // round up to 128 (= BN)
    __shared__ float red[256];
    const int tid = threadIdx.x;

    float m = -3.4e38f;
    for (int j = tid; j < len; j += 256) m = fmaxf(m, p[j]);
    red[tid] = m;
    __syncthreads();
    for (int s = 128; s > 0; s >>= 1) {
        if (tid < s) red[tid] = fmaxf(red[tid], red[tid + s]);
        __syncthreads();
    }
    m = red[0];
    __syncthreads();

    float sum = 0.0f;
    for (int j = tid; j < tend; j += 256) {
        if (j < len) {
            float e = expf(p[j] - m);
            p[j] = e;
            sum += e;
        } else {
            p[j] = 0.0f;
        }
    }
    red[tid] = sum;
    __syncthreads();
    for (int s = 128; s > 0; s >>= 1) {
        if (tid < s) red[tid] += red[tid + s];
        __syncthreads();
    }
    const float inv = 1.0f / red[0];
    for (int j = tid; j < len; j += 256) p[j] *= inv;
}

// ---------------------------------------------------------------------------
extern "C" void kernel_launch(void* const* d_in, const int* in_sizes, int n_in,
                              void* d_out, int out_size)
{
    const float* x  = (const float*)d_in[0];
    const float* Wq = (const float*)d_in[1];
    const float* bq = (const float*)d_in[2];
    const float* Wk = (const float*)d_in[3];
    const float* bk = (const float*)d_in[4];
    const float* Wv = (const float*)d_in[5];
    const float* bv = (const float*)d_in[6];
    const float* Wo = (const float*)d_in[7];
    const float* bo = (const float*)d_in[8];

    float *Q, *K, *Vt, *O, *S, *Wt;
    cudaGetSymbolAddress((void**)&Q,  g_Q);
    cudaGetSymbolAddress((void**)&K,  g_K);
    cudaGetSymbolAddress((void**)&Vt, g_Vt);
    cudaGetSymbolAddress((void**)&O,  g_O);
    cudaGetSymbolAddress((void**)&S,  g_S);
    cudaGetSymbolAddress((void**)&Wt, g_Wt);

    cudaFuncSetAttribute(mma_kernel<0>, cudaFuncAttributeMaxDynamicSharedMemorySize, SMEM_BYTES);
    cudaFuncSetAttribute(mma_kernel<1>, cudaFuncAttributeMaxDynamicSharedMemorySize, SMEM_BYTES);
    cudaFuncSetAttribute(mma_kernel<2>, cudaFuncAttributeMaxDynamicSharedMemorySize, SMEM_BYTES);
    cudaFuncSetAttribute(mma_kernel<3>, cudaFuncAttributeMaxDynamicSharedMemorySize, SMEM_BYTES);
    cudaFuncSetAttribute(mma_kernel<4>, cudaFuncAttributeMaxDynamicSharedMemorySize, SMEM_BYTES);

    // weight transposes (Wt[n][k] = W[k][n])
    dim3 tb(32, 8);
    dim3 tgw(CC / 32, CC / 32);
    transpose_kernel<<<tgw, tb>>>(Wq, Wt + 0 * (size_t)CC * CC, CC, CC);
    transpose_kernel<<<tgw, tb>>>(Wk, Wt + 1 * (size_t)CC * CC, CC, CC);
    transpose_kernel<<<tgw, tb>>>(Wv, Wt + 2 * (size_t)CC * CC, CC, CC);
    transpose_kernel<<<tgw, tb>>>(Wo, Wt + 3 * (size_t)CC * CC, CC, CC);

    // projections (RoPE fused for Q/K; V writes V^T directly)
    dim3 gproj(CC / BN, MTOT / BM, 1);
    mma_kernel<4><<<gproj, 256, SMEM_BYTES>>>(x, Wt + 0 * (size_t)CC * CC, bq, Q, CC, CC);
    mma_kernel<4><<<gproj, 256, SMEM_BYTES>>>(x, Wt + 1 * (size_t)CC * CC, bk, K, CC, CC);
    mma_kernel<1><<<gproj, 256, SMEM_BYTES>>>(x, Wt + 2 * (size_t)CC * CC, bv, Vt, CC, CC);

    // scores: S = QK^T * rsqrt(C), lower/diag tiles only
    dim3 gsc(TT / BN, TT / BM, NB);
    mma_kernel<2><<<gsc, 256, SMEM_BYTES>>>(Q, K, nullptr, S, CC, CC);

    softmax_kernel<<<MTOT, 256>>>(S);

    // O = P @ V
    dim3 gpv(CC / BN, TT / BM, NB);
    mma_kernel<3><<<gpv, 256, SMEM_BYTES>>>(S, Vt, nullptr, O, TT, MTOT);

    // out = O @ Wo + bo
    mma_kernel<0><<<gproj, 256, SMEM_BYTES>>>(O, Wt + 3 * (size_t)CC * CC, bo, (float*)d_out, CC, CC);

    (void)n_in; (void)out_size; (void)in_sizes;
}

// round 7
// speedup vs baseline: 1.0020x; 1.0019x over previous
#include <cuda_runtime.h>
#include <math.h>
#include <stdint.h>

// ===========================================================================
// Attention_49185965473896 — mma.sync tf32 (sm_100), round 5
//   B=4, T=2048, C=1024 fp32.
// Changes vs round 4:
//   - RoPE fused into Q/K projection epilogue (register-resident pairs)
//   - V projection writes V^T directly (smem-staged transposed epilogue)
//   - STAGES 5->4, __launch_bounds__(256,2) for 2 CTAs/SM
// ===========================================================================

#define TT 2048
#define CC 1024
#define NB 4
#define MTOT (NB * TT)

#define BM 128
#define BN 128
#define BK 16
#define PITCH 20                       // floats per smem row (16 data + 4 pad)
#define STAGES 4
#define STAGE_FLOATS ((BM + BN) * PITCH)           // 5120
#define SMEM_BYTES   (STAGES * STAGE_FLOATS * 4)   // 81920
#define TPITCH 133                     // transpose-stage pitch (conflict-free)

// Scratch (static device arrays; allocation is forbidden)
__device__ float g_Q [(size_t)NB * TT * CC];
__device__ float g_K [(size_t)NB * TT * CC];
__device__ float g_Vt[(size_t)CC * NB * TT];   // [C][B*T]
__device__ float g_O [(size_t)NB * TT * CC];
__device__ float g_S [(size_t)NB * TT * TT];
__device__ float g_Wt[(size_t)4 * CC * CC];

// ---------------------------------------------------------------------------
__device__ __forceinline__ uint32_t smem_u32(const void* p) {
    uint32_t a;
    asm("{ .reg .u64 t; cvta.to.shared.u64 t, %1; cvt.u32.u64 %0, t; }"
        : "=r"(a) : "l"(p));
    return a;
}
__device__ __forceinline__ void cp_async16(uint32_t s, const void* g) {
    asm volatile("cp.async.cg.shared.global [%0], [%1], 16;\n" :: "r"(s), "l"(g));
}
__device__ __forceinline__ uint32_t f2tf(float x) {
    uint32_t r;
    asm("cvt.rna.tf32.f32 %0, %1;" : "=r"(r) : "f"(x));
    return r;
}
__device__ __forceinline__ void mma8(float& c0, float& c1, float& c2, float& c3,
                                     uint32_t a0, uint32_t a1, uint32_t a2, uint32_t a3,
                                     uint32_t b0, uint32_t b1) {
    asm volatile(
        "mma.sync.aligned.m16n8k8.row.col.f32.tf32.tf32.f32 "
        "{%0,%1,%2,%3}, {%4,%5,%6,%7}, {%8,%9}, {%0,%1,%2,%3};"
        : "+f"(c0), "+f"(c1), "+f"(c2), "+f"(c3)
        : "r"(a0), "r"(a1), "r"(a2), "r"(a3), "r"(b0), "r"(b1));
}

// ---------------------------------------------------------------------------
// MODE: 0 = PROJ (+bias)
//       1 = PROJ -> V^T (+bias, transposed smem-staged epilogue)
//       2 = SCORES (scale; tiles with n0>m0 skipped)
//       3 = PV (K truncated at m0+BM)
//       4 = PROJ + RoPE (+bias, in-register rotation)
// ---------------------------------------------------------------------------
template<int MODE>
__global__ __launch_bounds__(256, 2) void mma_kernel(
    const float* __restrict__ A, const float* __restrict__ Bm,
    const float* __restrict__ bias, float* __restrict__ Out,
    int pitchA, int pitchB)
{
    const int m0 = blockIdx.y * BM;
    const int n0 = blockIdx.x * BN;
    const int z  = blockIdx.z;

    if (MODE == 2 && n0 > m0) return;   // strictly-upper tile: nothing to do

    extern __shared__ float smem[];
    const int tid = threadIdx.x;
    const int wid = tid >> 5;
    const int lane = tid & 31;
    const int g = lane >> 2;            // group id 0..7
    const int tg = lane & 3;            // thread-in-group 0..3
    const int wm = wid & 3;             // warp row (4 x 32 rows)
    const int wn = wid >> 2;            // warp col (2 x 64 cols)

    // geometry
    const float* Abase;
    const float* Bbase;
    float* OutB;
    int Klen, outPitch;
    if (MODE == 0 || MODE == 1 || MODE == 4) {
        Abase = A + (size_t)m0 * pitchA;
        Bbase = Bm + (size_t)n0 * pitchB;
        OutB = Out; Klen = CC; outPitch = CC;
    } else if (MODE == 2) {
        Abase = A + ((size_t)z * TT + m0) * pitchA;
        Bbase = Bm + ((size_t)z * TT + n0) * pitchB;
        OutB = Out + (size_t)z * TT * TT; Klen = CC; outPitch = TT;
    } else {
        Abase = A + ((size_t)z * TT + m0) * pitchA;
        Bbase = Bm + (size_t)n0 * pitchB + (size_t)z * TT;  // Vt: [C][B*T]
        OutB = Out + (size_t)z * TT * CC; Klen = m0 + BM; outPitch = CC;
    }
    const int KT = Klen / BK;

    float acc[2][8][4];
    #pragma unroll
    for (int mt = 0; mt < 2; mt++)
        #pragma unroll
        for (int nt = 0; nt < 8; nt++)
            #pragma unroll
            for (int c = 0; c < 4; c++) acc[mt][nt][c] = 0.0f;

    // per-thread load geometry: 2 x 16B for A, 2 x 16B for B
    const int r0c = tid >> 2;
    const int o0c = (tid & 3) * 4;
    const int r1c = (tid + 256) >> 2;
    const int o1c = o0c;

    auto load_stage = [&](int kt, int slot) {
        float* dA = smem + slot * STAGE_FLOATS;
        float* dB = dA + BM * PITCH;
        const int k0 = kt * BK;
        cp_async16(smem_u32(dA + r0c * PITCH + o0c), Abase + (size_t)r0c * pitchA + k0 + o0c);
        cp_async16(smem_u32(dA + r1c * PITCH + o1c), Abase + (size_t)r1c * pitchA + k0 + o1c);
        cp_async16(smem_u32(dB + r0c * PITCH + o0c), Bbase + (size_t)r0c * pitchB + k0 + o0c);
        cp_async16(smem_u32(dB + r1c * PITCH + o1c), Bbase + (size_t)r1c * pitchB + k0 + o1c);
    };

    // prologue: prefetch STAGES-1 stages (KT >= 8 always)
    #pragma unroll
    for (int s = 0; s < STAGES - 1; s++) {
        load_stage(s, s);
        asm volatile("cp.async.commit_group;\n" ::);
    }

    for (int kt = 0; kt < KT; kt++) {
        asm volatile("cp.async.wait_group %0;\n" :: "n"(STAGES - 2));
        __syncthreads();

        const int nf = kt + STAGES - 1;
        if (nf < KT) load_stage(nf, nf % STAGES);
        asm volatile("cp.async.commit_group;\n" ::);

        const float* sA = smem + (kt % STAGES) * STAGE_FLOATS;
        const float* sB = sA + BM * PITCH;

        #pragma unroll
        for (int ks = 0; ks < 2; ks++) {
            uint32_t af[2][4], bf[8][2];
            #pragma unroll
            for (int mt = 0; mt < 2; mt++) {
                const float* p = sA + (wm * 32 + mt * 16 + g) * PITCH + ks * 8 + tg;
                af[mt][0] = f2tf(p[0]);
                af[mt][1] = f2tf(p[8 * PITCH]);
                af[mt][2] = f2tf(p[4]);
                af[mt][3] = f2tf(p[8 * PITCH + 4]);
            }
            #pragma unroll
            for (int nt = 0; nt < 8; nt++) {
                const float* p = sB + (wn * 64 + nt * 8 + g) * PITCH + ks * 8 + tg;
                bf[nt][0] = f2tf(p[0]);
                bf[nt][1] = f2tf(p[4]);
            }
            #pragma unroll
            for (int mt = 0; mt < 2; mt++)
                #pragma unroll
                for (int nt = 0; nt < 8; nt++)
                    mma8(acc[mt][nt][0], acc[mt][nt][1], acc[mt][nt][2], acc[mt][nt][3],
                         af[mt][0], af[mt][1], af[mt][2], af[mt][3],
                         bf[nt][0], bf[nt][1]);
        }
    }

    // ------------------------- epilogues -------------------------
    const float scale = rsqrtf((float)CC);

    if (MODE == 1) {
        // V^T path: stage tile in smem, write transposed coalesced.
        __syncthreads();   // mainloop smem fully consumed
        float* stage = smem;   // 128 x TPITCH floats = 68096 B < SMEM_BYTES
        #pragma unroll
        for (int mt = 0; mt < 2; mt++) {
            const int r = wm * 32 + mt * 16 + g;
            #pragma unroll
            for (int nt = 0; nt < 8; nt++) {
                const int cl = wn * 64 + nt * 8 + 2 * tg;
                const float b0 = __ldg(&bias[n0 + cl]);
                const float b1 = __ldg(&bias[n0 + cl + 1]);
                stage[r * TPITCH + cl]           = acc[mt][nt][0] + b0;
                stage[r * TPITCH + cl + 1]       = acc[mt][nt][1] + b1;
                stage[(r + 8) * TPITCH + cl]     = acc[mt][nt][2] + b0;
                stage[(r + 8) * TPITCH + cl + 1] = acc[mt][nt][3] + b1;
            }
        }
        __syncthreads();
        const int tl = tid & 127;
        const int nh = tid >> 7;
        #pragma unroll 4
        for (int it = 0; it < 64; it++) {
            const int nl = it * 2 + nh;
            Out[(size_t)(n0 + nl) * MTOT + m0 + tl] = stage[tl * TPITCH + nl];
        }
        return;
    }

    #pragma unroll
    for (int mt = 0; mt < 2; mt++) {
        const int row = m0 + wm * 32 + mt * 16 + g;
        #pragma unroll
        for (int nt = 0; nt < 8; nt++) {
            const int col = n0 + wn * 64 + nt * 8 + 2 * tg;
            float c0 = acc[mt][nt][0], c1 = acc[mt][nt][1];
            float c2 = acc[mt][nt][2], c3 = acc[mt][nt][3];
            if (MODE == 0 || MODE == 4) {
                const float b0 = __ldg(&bias[col]);
                const float b1 = __ldg(&bias[col + 1]);
                c0 += b0; c1 += b1; c2 += b0; c3 += b1;
            }
            if (MODE == 4) {
                // interleaved RoPE: (c0,c1) pair at t=row, (c2,c3) at t=row+8
                const float invf = powf(10000.0f, -(float)col / (float)CC);
                const int t = row & (TT - 1);
                float s0, co0, s8, co8;
                sincosf((float)t * invf, &s0, &co0);
                sincosf((float)(t + 8) * invf, &s8, &co8);
                const float e0 = c0, o0 = c1, e8 = c2, o8 = c3;
                c0 = e0 * co0 - o0 * s0;
                c1 = o0 * co0 + e0 * s0;
                c2 = e8 * co8 - o8 * s8;
                c3 = o8 * co8 + e8 * s8;
            }
            if (MODE == 2) {
                c0 *= scale; c1 *= scale; c2 *= scale; c3 *= scale;
            }
            *reinterpret_cast<float2*>(&OutB[(size_t)row * outPitch + col]) =
                make_float2(c0, c1);
            *reinterpret_cast<float2*>(&OutB[(size_t)(row + 8) * outPitch + col]) =
                make_float2(c2, c3);
        }
    }
}

// ---------------------------------------------------------------------------
// Transpose: dst[c][r] = src[r][c], R x Ccols -> Ccols x R (both mult of 32)
// ---------------------------------------------------------------------------
__global__ void transpose_kernel(const float* __restrict__ src, float* __restrict__ dst,
                                 int R, int Ccols)
{
    __shared__ float tile[32][33];
    const int tx = threadIdx.x, ty = threadIdx.y;
    const int x = blockIdx.x * 32 + tx;
    const int y = blockIdx.y * 32 + ty;
    #pragma unroll
    for (int i = 0; i < 32; i += 8)
        tile[ty + i][tx] = src[(size_t)(y + i) * Ccols + x];
    __syncthreads();
    const int x2 = blockIdx.y * 32 + tx;
    const int y2 = blockIdx.x * 32 + ty;
    #pragma unroll
    for (int i = 0; i < 32; i += 8)
        dst[(size_t)(y2 + i) * R + x2] = tile[tx][ty + i];
}

// ---------------------------------------------------------------------------
// Causal softmax over valid prefix [0, i]; zero-fills (i, tile_end).
// ---------------------------------------------------------------------------
__global__ __launch_bounds__(256) void softmax_kernel(float* __restrict__ S)
{
    float* p = S + (size_t)blockIdx.x * TT;
    const int i = blockIdx.x & (TT - 1);
    const int len = i + 1;
    const int tend = ((i >> 7) + 1) << 7;   // round up to 128 (= BN)
    __shared__ float red[256];
    const int tid = threadIdx.x;

    float m = -3.4e38f;
    for (int j = tid; j < len; j += 256) m = fmaxf(m, p[j]);
    red[tid] = m;
    __syncthreads();
    for (int s = 128; s > 0; s >>= 1) {
        if (tid < s) red[tid] = fmaxf(red[tid], red[tid + s]);
        __syncthreads();
    }
    m = red[0];
    __syncthreads();

    float sum = 0.0f;
    for (int j = tid; j < tend; j += 256) {
        if (j < len) {
            float e = expf(p[j] - m);
            p[j] = e;
            sum += e;
        } else {
            p[j] = 0.0f;
        }
    }
    red[tid] = sum;
    __syncthreads();
    for (int s = 128; s > 0; s >>= 1) {
        if (tid < s) red[tid] += red[tid + s];
        __syncthreads();
    }
    const float inv = 1.0f / red[0];
    for (int j = tid; j < len; j += 256) p[j] *= inv;
}

// ---------------------------------------------------------------------------
extern "C" void kernel_launch(void* const* d_in, const int* in_sizes, int n_in,
                              void* d_out, int out_size)
{
    const float* x  = (const float*)d_in[0];
    const float* Wq = (const float*)d_in[1];
    const float* bq = (const float*)d_in[2];
    const float* Wk = (const float*)d_in[3];
    const float* bk = (const float*)d_in[4];
    const float* Wv = (const float*)d_in[5];
    const float* bv = (const float*)d_in[6];
    const float* Wo = (const float*)d_in[7];
    const float* bo = (const float*)d_in[8];

    float *Q, *K, *Vt, *O, *S, *Wt;
    cudaGetSymbolAddress((void**)&Q,  g_Q);
    cudaGetSymbolAddress((void**)&K,  g_K);
    cudaGetSymbolAddress((void**)&Vt, g_Vt);
    cudaGetSymbolAddress((void**)&O,  g_O);
    cudaGetSymbolAddress((void**)&S,  g_S);
    cudaGetSymbolAddress((void**)&Wt, g_Wt);

    cudaFuncSetAttribute(mma_kernel<0>, cudaFuncAttributeMaxDynamicSharedMemorySize, SMEM_BYTES);
    cudaFuncSetAttribute(mma_kernel<1>, cudaFuncAttributeMaxDynamicSharedMemorySize, SMEM_BYTES);
    cudaFuncSetAttribute(mma_kernel<2>, cudaFuncAttributeMaxDynamicSharedMemorySize, SMEM_BYTES);
    cudaFuncSetAttribute(mma_kernel<3>, cudaFuncAttributeMaxDynamicSharedMemorySize, SMEM_BYTES);
    cudaFuncSetAttribute(mma_kernel<4>, cudaFuncAttributeMaxDynamicSharedMemorySize, SMEM_BYTES);

    // weight transposes (Wt[n][k] = W[k][n])
    dim3 tb(32, 8);
    dim3 tgw(CC / 32, CC / 32);
    transpose_kernel<<<tgw, tb>>>(Wq, Wt + 0 * (size_t)CC * CC, CC, CC);
    transpose_kernel<<<tgw, tb>>>(Wk, Wt + 1 * (size_t)CC * CC, CC, CC);
    transpose_kernel<<<tgw, tb>>>(Wv, Wt + 2 * (size_t)CC * CC, CC, CC);
    transpose_kernel<<<tgw, tb>>>(Wo, Wt + 3 * (size_t)CC * CC, CC, CC);

    // projections (RoPE fused for Q/K; V writes V^T directly)
    dim3 gproj(CC / BN, MTOT / BM, 1);
    mma_kernel<4><<<gproj, 256, SMEM_BYTES>>>(x, Wt + 0 * (size_t)CC * CC, bq, Q, CC, CC);
    mma_kernel<4><<<gproj, 256, SMEM_BYTES>>>(x, Wt + 1 * (size_t)CC * CC, bk, K, CC, CC);
    mma_kernel<1><<<gproj, 256, SMEM_BYTES>>>(x, Wt + 2 * (size_t)CC * CC, bv, Vt, CC, CC);

    // scores: S = QK^T * rsqrt(C), lower/diag tiles only
    dim3 gsc(TT / BN, TT / BM, NB);
    mma_kernel<2><<<gsc, 256, SMEM_BYTES>>>(Q, K, nullptr, S, CC, CC);

    softmax_kernel<<<MTOT, 256>>>(S);

    // O = P @ V
    dim3 gpv(CC / BN, TT / BM, NB);
    mma_kernel<3><<<gpv, 256, SMEM_BYTES>>>(S, Vt, nullptr, O, TT, MTOT);

    // out = O @ Wo + bo
    mma_kernel<0><<<gproj, 256, SMEM_BYTES>>>(O, Wt + 3 * (size_t)CC * CC, bo, (float*)d_out, CC, CC);

    (void)n_in; (void)out_size; (void)in_sizes;
}